// round 3
// baseline (speedup 1.0000x reference)
#include <cuda_runtime.h>

// RNNBlock: out = relu( RNN_backwards(x; w_in, w_rec, b_rnn) @ w_d + b_d )
// fp32 throughout, packed f32x2 FMA path (2x fp32 rate on Blackwell).

typedef unsigned long long u64;

#define B_TOT    32768
#define T_STEPS  79
#define F_IN     16
#define C_DIM    256
#define BM       128      // batch rows per CTA
#define NTHREADS 512      // 16 warps; each warp owns 8 batch rows

#define SMEM_FLOATS (BM*C_DIM + 32*C_DIM + F_IN*C_DIM)   // h + w_chunk + w_in
#define SMEM_BYTES  (SMEM_FLOATS * 4)                     // 176 KB

__device__ __forceinline__ u64 pack2(float lo, float hi) {
    u64 r; asm("mov.b64 %0, {%1, %2};" : "=l"(r) : "f"(lo), "f"(hi)); return r;
}
__device__ __forceinline__ u64 dup2(float v) {
    u64 r; asm("mov.b64 %0, {%1, %1};" : "=l"(r) : "f"(v)); return r;
}
__device__ __forceinline__ void unpack2(u64 v, float& lo, float& hi) {
    asm("mov.b64 {%0, %1}, %2;" : "=f"(lo), "=f"(hi) : "l"(v));
}
__device__ __forceinline__ void fma2(u64& d, u64 a, u64 b) {
    asm("fma.rn.f32x2 %0, %1, %2, %0;" : "+l"(d) : "l"(a), "l"(b));
}

// acc[b][p] += h[bloc+b][k] * W[k][c0+2p .. c0+2p+1]  for all k in 0..255,
// with W streamed from global in 32-row (32 KB) SMEM chunks, next chunk
// register-prefetched so the LDG latency overlaps compute.
__device__ __forceinline__ void mm256(
    const float* __restrict__ wglob,
    float* __restrict__ w_sm,
    const float* __restrict__ hbase,      // h_sm + bloc*C_DIM
    int c0, int tid, u64 acc[8][4])
{
    float4 pf0, pf1, pf2, pf3;
    {
        const float4* src = (const float4*)wglob;
        pf0 = src[tid];               pf1 = src[tid + NTHREADS];
        pf2 = src[tid + 2*NTHREADS];  pf3 = src[tid + 3*NTHREADS];
    }
    #pragma unroll 1
    for (int kc = 0; kc < 8; ++kc) {
        __syncthreads();                      // previous chunk fully consumed
        {
            float4* dst = (float4*)w_sm;
            dst[tid]               = pf0;
            dst[tid + NTHREADS]    = pf1;
            dst[tid + 2*NTHREADS]  = pf2;
            dst[tid + 3*NTHREADS]  = pf3;
        }
        if (kc < 7) {                          // prefetch next chunk
            const float4* src = (const float4*)(wglob + (kc + 1) * 32 * C_DIM);
            pf0 = src[tid];               pf1 = src[tid + NTHREADS];
            pf2 = src[tid + 2*NTHREADS];  pf3 = src[tid + 3*NTHREADS];
        }
        __syncthreads();                      // chunk visible
        const float* hk = hbase + kc * 32;
        #pragma unroll 2
        for (int kk = 0; kk < 32; ++kk) {
            const u64* wrow = (const u64*)(w_sm + kk * C_DIM + c0);
            u64 wp0 = wrow[0], wp1 = wrow[1], wp2 = wrow[2], wp3 = wrow[3];
            #pragma unroll
            for (int b = 0; b < 8; ++b) {
                u64 hd = dup2(hk[b * C_DIM + kk]);   // warp-broadcast LDS
                fma2(acc[b][0], hd, wp0);
                fma2(acc[b][1], hd, wp1);
                fma2(acc[b][2], hd, wp2);
                fma2(acc[b][3], hd, wp3);
            }
        }
    }
}

__global__ void __launch_bounds__(NTHREADS, 1)
rnn_fused(const float* __restrict__ x,     const float* __restrict__ w_in,
          const float* __restrict__ w_rec, const float* __restrict__ b_rnn,
          const float* __restrict__ w_d,   const float* __restrict__ b_d,
          float* __restrict__ out)
{
    extern __shared__ float smem[];
    float* h_sm  = smem;                    // BM  x 256  (128 KB)
    float* w_sm  = smem + BM * C_DIM;       // 32  x 256  (32 KB)  weight chunk
    float* wi_sm = w_sm + 32 * C_DIM;       // 16  x 256  (16 KB)  w_in

    const int tid  = threadIdx.x;
    const int lane = tid & 31;
    const int wid  = tid >> 5;
    const int c0   = lane << 3;             // 8 columns per lane (4 f32x2 pairs)
    const int bloc = wid  << 3;             // 8 batch rows per warp
    const long bglob = (long)blockIdx.x * BM + bloc;

    // stage w_in once
    {
        const float4* src = (const float4*)w_in;
        float4* dst = (float4*)wi_sm;
        for (int i = tid; i < (F_IN * C_DIM) / 4; i += NTHREADS) dst[i] = src[i];
    }
    u64 bp[4];
    #pragma unroll
    for (int p = 0; p < 4; ++p)
        bp[p] = pack2(b_rnn[c0 + 2*p], b_rnn[c0 + 2*p + 1]);
    __syncthreads();

    u64 acc[8][4];
    const float* hbase = h_sm + bloc * C_DIM;

    for (int s = 0; s < T_STEPS; ++s) {
        const int t = T_STEPS - 1 - s;      // go_backwards

        // ---- init acc = b_rnn + x[:,t,:] @ w_in  (warp-local, shfl bcast) ----
        float xr0, xr1, xr2, xr3;
        {
            const int r = lane >> 2, q = lane & 3;   // lane holds quad q of row r
            const float4 xq = *(const float4*)(x + ((bglob + r) * T_STEPS + t) * F_IN + q * 4);
            xr0 = xq.x; xr1 = xq.y; xr2 = xq.z; xr3 = xq.w;
        }
        #pragma unroll
        for (int b = 0; b < 8; ++b)
            #pragma unroll
            for (int p = 0; p < 4; ++p) acc[b][p] = bp[p];

        #pragma unroll
        for (int f = 0; f < F_IN; ++f) {
            const u64* wrow = (const u64*)(wi_sm + f * C_DIM + c0);
            u64 wp0 = wrow[0], wp1 = wrow[1], wp2 = wrow[2], wp3 = wrow[3];
            float xsel = ((f & 3) == 0) ? xr0 : ((f & 3) == 1) ? xr1
                       : ((f & 3) == 2) ? xr2 : xr3;            // const after unroll
            #pragma unroll
            for (int b = 0; b < 8; ++b) {
                float xv = __shfl_sync(0xffffffffu, xsel, (b << 2) | (f >> 2));
                u64 xd = dup2(xv);
                fma2(acc[b][0], xd, wp0);
                fma2(acc[b][1], xd, wp1);
                fma2(acc[b][2], xd, wp2);
                fma2(acc[b][3], xd, wp3);
            }
        }

        // ---- recurrent term: acc += h @ w_rec (skip at s=0: h==0) ----
        if (s > 0) mm256(w_rec, w_sm, hbase, c0, tid, acc);

        // ---- relu + writeback h (warp-private rows: no barrier needed) ----
        #pragma unroll
        for (int b = 0; b < 8; ++b)
            #pragma unroll
            for (int p = 0; p < 4; ++p) {
                float lo, hi; unpack2(acc[b][p], lo, hi);
                lo = fmaxf(lo, 0.f); hi = fmaxf(hi, 0.f);
                *(u64*)(h_sm + (bloc + b) * C_DIM + c0 + 2*p) = pack2(lo, hi);
            }
    }

    // ---- dense head: out = relu(h_last @ w_d + b_d) ----
    #pragma unroll
    for (int p = 0; p < 4; ++p)
        bp[p] = pack2(b_d[c0 + 2*p], b_d[c0 + 2*p + 1]);
    #pragma unroll
    for (int b = 0; b < 8; ++b)
        #pragma unroll
        for (int p = 0; p < 4; ++p) acc[b][p] = bp[p];

    mm256(w_d, w_sm, hbase, c0, tid, acc);

    #pragma unroll
    for (int b = 0; b < 8; ++b) {
        float* orow = out + (bglob + b) * C_DIM;
        #pragma unroll
        for (int p = 0; p < 4; ++p) {
            float lo, hi; unpack2(acc[b][p], lo, hi);
            float2 v = make_float2(fmaxf(lo, 0.f), fmaxf(hi, 0.f));
            *(float2*)(orow + c0 + 2*p) = v;
        }
    }
}

extern "C" void kernel_launch(void* const* d_in, const int* in_sizes, int n_in,
                              void* d_out, int out_size)
{
    const float* x     = (const float*)d_in[0];
    const float* w_in  = (const float*)d_in[1];
    const float* w_rec = (const float*)d_in[2];
    const float* b_rnn = (const float*)d_in[3];
    const float* w_d   = (const float*)d_in[4];
    const float* b_d   = (const float*)d_in[5];
    float* out = (float*)d_out;

    // idempotent; safe under graph capture (not a stream op)
    cudaFuncSetAttribute(rnn_fused, cudaFuncAttributeMaxDynamicSharedMemorySize, SMEM_BYTES);

    rnn_fused<<<B_TOT / BM, NTHREADS, SMEM_BYTES>>>(x, w_in, w_rec, b_rnn, w_d, b_d, out);
}